// round 9
// baseline (speedup 1.0000x reference)
#include <cuda_runtime.h>
#include <cuda_fp16.h>
#include <cstdint>
#include <math.h>

// Problem shapes (fixed by setup_inputs)
#define NN 40000
#define EE 100000
#define DD 768
#define GG 128
#define D3 2304
#define SS 589824                     // 768*768 (elements)

// ---------------- scratch (static device globals; allocation-free) ----------
__device__ static __half g_xh [(size_t)NN * DD];        // x in fp16
__device__ static __half g_h0 [(size_t)NN * DD];        // h0 / t
__device__ static __half g_emb3[(size_t)NN * D3];       // concat(h1,h2,h3)
__device__ static __half g_uv [(size_t)NN * 2 * DD];    // [u | v] per node
__device__ static __half g_yh [(size_t)GG * DD];        // y in fp16
__device__ static __half g_yp [(size_t)GG * DD];        // leaky(y@py+b)
__device__ static __half g_w  [(size_t)GG * DD];        // yp@W3 + pc1_b per graph
__device__ static __half g_wT [8257536];                // weights: 14 * 768*768 halves
__device__ static float  g_buv[2 * DD];                 // bias for uv GEMM
__device__ static float  g_zero[2 * DD];                // zero bias (zero-init)
__device__ static int    g_cnt[10 * 320];               // per (layer, m-block) counters
__device__ static int    g_ticket;                      // work ticket

// ---------------- helpers ----------------------------------------------------
__device__ __forceinline__ uint32_t smem_u32(const void* p) {
    uint32_t a;
    asm("{ .reg .u64 t; cvta.to.shared.u64 t, %1; cvt.u32.u64 %0, t; }" : "=r"(a) : "l"(p));
    return a;
}

__device__ __forceinline__ void cp_async16(uint32_t dst, const void* src, bool pred) {
    int sz = pred ? 16 : 0;
    asm volatile("cp.async.cg.shared.global [%0], [%1], 16, %2;"
                 :: "r"(dst), "l"(src), "r"(sz) : "memory");
}
#define CP_COMMIT() asm volatile("cp.async.commit_group;" ::: "memory")
#define CP_WAIT(n)  asm volatile("cp.async.wait_group %0;" :: "n"(n) : "memory")

__device__ __forceinline__ void ldsm_x4(uint32_t& r0, uint32_t& r1, uint32_t& r2, uint32_t& r3,
                                        uint32_t addr) {
    asm volatile("ldmatrix.sync.aligned.m8n8.x4.shared.b16 {%0,%1,%2,%3}, [%4];"
                 : "=r"(r0), "=r"(r1), "=r"(r2), "=r"(r3) : "r"(addr));
}

__device__ __forceinline__ void mma_f16(float d[4], const uint32_t a[4], const uint32_t b[2]) {
    asm volatile(
        "mma.sync.aligned.m16n8k16.row.col.f32.f16.f16.f32 "
        "{%0,%1,%2,%3}, {%4,%5,%6,%7}, {%8,%9}, {%0,%1,%2,%3};"
        : "+f"(d[0]), "+f"(d[1]), "+f"(d[2]), "+f"(d[3])
        : "r"(a[0]), "r"(a[1]), "r"(a[2]), "r"(a[3]), "r"(b[0]), "r"(b[1]));
}

__device__ __forceinline__ void wait_cnt(const int* p, int need) {
    while (true) {
        int v;
        asm volatile("ld.acquire.gpu.global.b32 %0, [%1];" : "=r"(v) : "l"(p) : "memory");
        if (v >= need) break;
        __nanosleep(128);
    }
}

__device__ __forceinline__ void post_cnt(int* p) {
    asm volatile("red.release.gpu.global.add.s32 [%0], 1;" :: "l"(p) : "memory");
}

#define SW(o) ((o) ^ (((o) >> 3) & 0x70))   // SW128 byte swizzle within 1KB atom

// ---------------- fp16 mma.sync GEMM tile (R5/R8 proven core) -----------------
#define BM 128
#define BN 128
#define BK 64
#define TILE_BYTES 16384                   // 128 rows * 128B
#define STAGE_BYTES (2 * TILE_BYTES)       // A then B: 32 KB
#define NSTAGE 3
#define DYN_BYTES (NSTAGE * STAGE_BYTES)   // 96 KB -> 2 CTAs/SM

__device__ __forceinline__ void gemm_tile(
    const __half* __restrict__ A, int lda,
    const __half* __restrict__ Bt,
    const float* __restrict__ bias,
    __half* __restrict__ C, int ldc,
    int M, int K, int act, int m0, int n0, char* sh)
{
    const int tid = threadIdx.x;
    const int wid = tid >> 5, lane = tid & 31;
    const int g = lane >> 2, t = lane & 3;
    const int wm = wid & 3, wn = wid >> 2;      // 4 M-warps x 2 N-warps

    const int nk = K / BK;
    const uint32_t shbase = smem_u32(sh);

    const int lrow0 = tid >> 3;           // +32*i
    const int lchB  = (tid & 7) * 16;
    const int lchH  = (tid & 7) * 8;

    auto issue_tile = [&](int kt) {
        if (kt < nk) {
            uint32_t As = shbase + (uint32_t)(kt % NSTAGE) * STAGE_BYTES;
            uint32_t Bs = As + TILE_BYTES;
            #pragma unroll
            for (int i = 0; i < 4; i++) {
                int row = lrow0 + i * 32;
                int gr = m0 + row;
                cp_async16(As + SW((uint32_t)(row * 128 + lchB)),
                           A + (long long)gr * lda + kt * BK + lchH, gr < M);
                cp_async16(Bs + SW((uint32_t)(row * 128 + lchB)),
                           Bt + (long long)(n0 + row) * K + kt * BK + lchH, true);
            }
        }
        CP_COMMIT();
    };

    float acc[2][8][4];
    #pragma unroll
    for (int i = 0; i < 2; i++)
        #pragma unroll
        for (int j = 0; j < 8; j++)
            #pragma unroll
            for (int q = 0; q < 4; q++) acc[i][j][q] = 0.f;

    issue_tile(0);
    issue_tile(1);

    const int lmRow = lane & 15;
    const int lmHi  = (lane & 16) ? 16 : 0;

    #pragma unroll 1
    for (int kt = 0; kt < nk; ++kt) {
        CP_WAIT(1);
        __syncthreads();
        issue_tile(kt + 2);

        uint32_t As = shbase + (uint32_t)(kt % NSTAGE) * STAGE_BYTES;
        uint32_t Bs = As + TILE_BYTES;

        #pragma unroll
        for (int ks = 0; ks < 4; ++ks) {
            const int kb = ks * 32 + lmHi;
            uint32_t a[2][4], b[8][2];
            #pragma unroll
            for (int mt = 0; mt < 2; ++mt) {
                int row = wm * 32 + mt * 16 + lmRow;
                ldsm_x4(a[mt][0], a[mt][1], a[mt][2], a[mt][3],
                        As + SW((uint32_t)(row * 128 + kb)));
            }
            #pragma unroll
            for (int nq = 0; nq < 4; ++nq) {
                int row = wn * 64 + nq * 16 + lmRow;
                ldsm_x4(b[2*nq][0], b[2*nq+1][0], b[2*nq][1], b[2*nq+1][1],
                        Bs + SW((uint32_t)(row * 128 + kb)));
            }
            #pragma unroll
            for (int mt = 0; mt < 2; ++mt)
                #pragma unroll
                for (int nt = 0; nt < 8; ++nt)
                    mma_f16(acc[mt][nt], a[mt], b[nt]);
        }
    }

    // ---- epilogue: bias + activation + fp16 store ----
    #pragma unroll
    for (int mt = 0; mt < 2; ++mt) {
        int row0 = m0 + wm * 32 + mt * 16 + g;
        #pragma unroll
        for (int nt = 0; nt < 8; ++nt) {
            int col = n0 + wn * 64 + nt * 8 + t * 2;
            float2 bb = *(const float2*)(bias + col);
            float v0 = acc[mt][nt][0] + bb.x;
            float v1 = acc[mt][nt][1] + bb.y;
            float v2 = acc[mt][nt][2] + bb.x;
            float v3 = acc[mt][nt][3] + bb.y;
            if (act == 1) {
                v0 = fmaxf(v0, 0.f); v1 = fmaxf(v1, 0.f);
                v2 = fmaxf(v2, 0.f); v3 = fmaxf(v3, 0.f);
            } else if (act == 2) {
                v0 = (v0 > 0.f) ? v0 : 0.4f * v0;  v1 = (v1 > 0.f) ? v1 : 0.4f * v1;
                v2 = (v2 > 0.f) ? v2 : 0.4f * v2;  v3 = (v3 > 0.f) ? v3 : 0.4f * v3;
            }
            if (row0 < M)
                *(__half2*)(C + (long long)row0 * ldc + col) =
                    __float22half2_rn(make_float2(v0, v1));
            if (row0 + 8 < M)
                *(__half2*)(C + (long long)(row0 + 8) * ldc + col) =
                    __float22half2_rn(make_float2(v2, v3));
        }
    }
}

// ---------------- persistent dependency-driven scheduler ----------------------
// Ticket layout (topological order):
//  [0,72)        LC   composite wt_uv = wt_W12 @ o2h   (12m x 6n), no deps
//  [72,385)      CVT  x fp32->fp16, 313 m-tiles, no deps
//  [385,391)     YP   yp GEMM (1m x 6n), no deps
//  [391,397)     WG   w  GEMM (1m x 6n), dep: YP done
//  [397,2275)    AH   dep: CVT[m]
//  [2275,4153)   C0   dep: AH[m]==6
//  [4153,6031)   C1   dep: C0[m]==6
//  [6031,7909)   C2   dep: C1[m]==6
//  [7909,9787)   O1   dep: C2[m]==6   (K=2304)
//  [9787,13543)  UV   dep: O1[m]==6 && LC total==72  (12 n-blocks)
#define T_TOTAL 13543
#define CMB 320

struct BiasPack { const float* x; const float* b[10]; };

__global__ __launch_bounds__(256, 2) void persistent_gemm(BiasPack P)
{
    extern __shared__ char sh[];
    __shared__ int sWork;
    const int tid = threadIdx.x;

    while (true) {
        if (tid == 0) sWork = atomicAdd(&g_ticket, 1);
        __syncthreads();
        int w = sWork;
        if (w >= T_TOTAL) return;

        int layer, m, n;
        if      (w < 72)   { layer = 0; m = w / 6; n = w % 6; }
        else if (w < 385)  { layer = 1; m = w - 72; n = 0; }
        else if (w < 391)  { layer = 2; m = 0; n = w - 385; }
        else if (w < 397)  { layer = 3; m = 0; n = w - 391; }
        else if (w < 2275) { int l = w - 397;  layer = 4; m = l / 6; n = l % 6; }
        else if (w < 4153) { int l = w - 2275; layer = 5; m = l / 6; n = l % 6; }
        else if (w < 6031) { int l = w - 4153; layer = 6; m = l / 6; n = l % 6; }
        else if (w < 7909) { int l = w - 6031; layer = 7; m = l / 6; n = l % 6; }
        else if (w < 9787) { int l = w - 7909; layer = 8; m = l / 6; n = l % 6; }
        else               { int l = w - 9787; layer = 9; m = l / 12; n = l % 12; }

        // ---- dependency wait ----
        if (tid == 0) {
            switch (layer) {
                case 3: wait_cnt(&g_cnt[2 * CMB], 6); break;
                case 4: wait_cnt(&g_cnt[1 * CMB + m], 1); break;
                case 5: wait_cnt(&g_cnt[4 * CMB + m], 6); break;
                case 6: wait_cnt(&g_cnt[5 * CMB + m], 6); break;
                case 7: wait_cnt(&g_cnt[6 * CMB + m], 6); break;
                case 8: wait_cnt(&g_cnt[7 * CMB + m], 6); break;
                case 9: wait_cnt(&g_cnt[8 * CMB + m], 6);
                        wait_cnt(&g_cnt[0], 72); break;
                default: break;
            }
        }
        __syncthreads();

        if (layer == 1) {
            // ---- x fp32 -> fp16 tile (128 rows) ----
            int m0 = m * BM;
            int rows = (NN - m0 < BM) ? (NN - m0) : BM;
            const float4* src = (const float4*)(P.x + (size_t)m0 * DD);
            __half2* dst = (__half2*)(g_xh + (size_t)m0 * DD);
            int n4 = rows * (DD / 4);
            for (int i = tid; i < n4; i += 256) {
                float4 v = src[i];
                dst[2 * i]     = __float22half2_rn(make_float2(v.x, v.y));
                dst[2 * i + 1] = __float22half2_rn(make_float2(v.z, v.w));
            }
        } else {
            const __half *A, *Bt; __half* C;
            const float* bias;
            int lda, ldc, K, act, Mrows;
            switch (layer) {
                case 0: A = g_wT + 5*SS;  lda = DD;  Bt = g_wT + 13*SS; C = g_wT + 11*SS;
                        ldc = DD;  K = DD;  act = 0; Mrows = 2*DD; bias = g_zero; break;
                case 2: A = g_yh;         lda = DD;  Bt = g_wT + 4*SS;  C = g_yp;
                        ldc = DD;  K = DD;  act = 2; Mrows = GG;   bias = P.b[2]; break;
                case 3: A = g_yp;         lda = DD;  Bt = g_wT + 7*SS;  C = g_w;
                        ldc = DD;  K = DD;  act = 0; Mrows = GG;   bias = P.b[3]; break;
                case 4: A = g_xh;         lda = DD;  Bt = g_wT;         C = g_h0;
                        ldc = DD;  K = DD;  act = 1; Mrows = NN;   bias = P.b[4]; break;
                case 5: A = g_h0;         lda = DD;  Bt = g_wT + SS;    C = g_emb3;
                        ldc = D3;  K = DD;  act = 1; Mrows = NN;   bias = P.b[5]; break;
                case 6: A = g_emb3;       lda = D3;  Bt = g_wT + 2*SS;  C = g_emb3 + DD;
                        ldc = D3;  K = DD;  act = 1; Mrows = NN;   bias = P.b[6]; break;
                case 7: A = g_emb3 + DD;  lda = D3;  Bt = g_wT + 3*SS;  C = g_emb3 + 2*DD;
                        ldc = D3;  K = DD;  act = 1; Mrows = NN;   bias = P.b[7]; break;
                case 8: A = g_emb3;       lda = D3;  Bt = g_wT + 8*SS;  C = g_h0;
                        ldc = DD;  K = D3;  act = 1; Mrows = NN;   bias = P.b[8]; break;
                default:A = g_h0;         lda = DD;  Bt = g_wT + 11*SS; C = g_uv;
                        ldc = 2*DD; K = DD; act = 0; Mrows = NN;   bias = g_buv;  break;
            }
            gemm_tile(A, lda, Bt, bias, C, ldc, Mrows, K, act, m * BM, n * BN, sh);
        }

        __syncthreads();
        if (tid == 0) {
            int idx = (layer == 0) ? 0 : (layer * CMB + m);
            __threadfence();
            post_cnt(&g_cnt[idx]);
        }
    }
}

__global__ __launch_bounds__(256) void init_counters()
{
    int i = blockIdx.x * 256 + threadIdx.x;
    if (i < 10 * CMB) g_cnt[i] = 0;
    if (i == 0) g_ticket = 0;
}

// ---------------- batched prep kernels ----------------------------------------
struct Ptr8 { const float* p[8]; };

// 8x 768x768 transposes: Wt[n*768 + k] = W[k*768 + n], fp16 out
__global__ __launch_bounds__(256) void transpose8(Ptr8 src, __half* dstBase)
{
    const float* W = src.p[blockIdx.z];
    __half* Wt = dstBase + (size_t)blockIdx.z * ((size_t)DD * DD);
    __shared__ float tb[32][33];
    int n0 = blockIdx.x * 32, k0 = blockIdx.y * 32;
    int x = threadIdx.x & 31, y = threadIdx.x >> 5;
    #pragma unroll
    for (int i = 0; i < 32; i += 8)
        tb[y + i][x] = W[(long long)(k0 + y + i) * DD + n0 + x];
    __syncthreads();
    #pragma unroll
    for (int i = 0; i < 32; i += 8)
        Wt[(long long)(n0 + y + i) * DD + k0 + x] = __float2half_rn(tb[x][y + i]);
}

// o1 transpose: [2304(K) x 768(N)] -> Wt[n*2304 + k]
__global__ __launch_bounds__(256) void transpose_o1(
    const float* __restrict__ W, __half* __restrict__ Wt)
{
    __shared__ float tb[32][33];
    int n0 = blockIdx.x * 32, k0 = blockIdx.y * 32;
    int x = threadIdx.x & 31, y = threadIdx.x >> 5;
    #pragma unroll
    for (int i = 0; i < 32; i += 8)
        tb[y + i][x] = W[(long long)(k0 + y + i) * DD + n0 + x];
    __syncthreads();
    #pragma unroll
    for (int i = 0; i < 32; i += 8)
        Wt[(long long)(n0 + y + i) * D3 + k0 + x] = __float2half_rn(tb[x][y + i]);
}

// fp32->fp16 flat convert of y and o2_W (x is converted inside persistent kernel)
__global__ __launch_bounds__(256) void convert_yo(
    const float* __restrict__ y, const float* __restrict__ o2W,
    __half* __restrict__ yh, __half* __restrict__ o2h)
{
    const long long ny = (long long)GG * DD;
    const long long nw = (long long)DD * DD;
    long long i = ((long long)blockIdx.x * 256 + threadIdx.x) * 4;
    const float* src; __half* dst; long long j;
    if (i < ny) { src = y; dst = yh; j = i; }
    else if (i < ny + nw) { src = o2W; dst = o2h; j = i - ny; }
    else return;
    float4 v = *(const float4*)(src + j);
    *(__half2*)(dst + j)     = __float22half2_rn(make_float2(v.x, v.y));
    *(__half2*)(dst + j + 2) = __float22half2_rn(make_float2(v.z, v.w));
}

// b_uv[n] = sum_k o2_b[k] * W12[n,k]  — one warp per n (wt_W1|wt_W2 contiguous)
__global__ __launch_bounds__(256) void bias_uv(
    const __half* __restrict__ wt_W12, const float* __restrict__ o2_b,
    float* __restrict__ buv)
{
    int gw = (blockIdx.x * 256 + threadIdx.x) >> 5;   // warp id = output n
    int lane = threadIdx.x & 31;
    if (gw >= 2 * DD) return;
    const __half2* wrow = (const __half2*)(wt_W12 + (long long)gw * DD);
    float s = 0.f;
    #pragma unroll
    for (int i = lane; i < DD / 2; i += 32) {
        float2 f = __half22float2(wrow[i]);
        s = fmaf(f.x, o2_b[2 * i], s);
        s = fmaf(f.y, o2_b[2 * i + 1], s);
    }
    #pragma unroll
    for (int off = 16; off > 0; off >>= 1)
        s += __shfl_xor_sync(0xffffffffu, s, off);
    if (lane == 0) buv[gw] = s;
}

// ---------------- fused edge head ---------------------------------------------
__global__ __launch_bounds__(256) void edge_head(
    const __half* __restrict__ uv, const __half* __restrict__ w,
    const int* __restrict__ edge_index, const int* __restrict__ batch,
    const float* __restrict__ pc2W /*[768,2]*/, const float* __restrict__ b2,
    const float* __restrict__ lab, float* __restrict__ out, int E)
{
    __shared__ float w0[DD];
    __shared__ float w1[DD];
    for (int i = threadIdx.x; i < DD; i += blockDim.x) {
        w0[i] = pc2W[2 * i];
        w1[i] = pc2W[2 * i + 1];
    }
    __syncthreads();

    int warp = threadIdx.x >> 5;
    int lane = threadIdx.x & 31;
    int e = blockIdx.x * 8 + warp;
    if (e >= E) return;

    int src = edge_index[e];
    int dst = edge_index[E + e];
    int gph = batch[src];

    const __half2* ur = (const __half2*)(uv + (long long)src * (2 * DD));
    const __half2* vr = (const __half2*)(uv + (long long)dst * (2 * DD) + DD);
    const __half2* wr = (const __half2*)(w  + (long long)gph * DD);

    float a0 = 0.f, a1 = 0.f;
    #pragma unroll
    for (int i = 0; i < 12; i++) {
        int k = lane + i * 32;
        float2 fu = __half22float2(ur[k]);
        float2 fv = __half22float2(vr[k]);
        float2 fw = __half22float2(wr[k]);
        float q0 = fmaxf(fu.x + fv.x + fw.x, 0.f);
        float q1 = fmaxf(fu.y + fv.y + fw.y, 0.f);
        a0 = fmaf(q0, w0[2*k], a0);   a0 = fmaf(q1, w0[2*k+1], a0);
        a1 = fmaf(q0, w1[2*k], a1);   a1 = fmaf(q1, w1[2*k+1], a1);
    }
    #pragma unroll
    for (int off = 16; off > 0; off >>= 1) {
        a0 += __shfl_xor_sync(0xffffffffu, a0, off);
        a1 += __shfl_xor_sync(0xffffffffu, a1, off);
    }
    if (lane == 0) {
        out[2 * e]     = 1.f / (1.f + expf(-(a0 + b2[0])));
        out[2 * e + 1] = 1.f / (1.f + expf(-(a1 + b2[1])));
        out[2 * E + e] = lab[e];
    }
}

// ---------------- host launch ------------------------------------------------
static __half *p_xh = nullptr, *p_yh = nullptr, *p_uv = nullptr, *p_w = nullptr,
              *p_wT = nullptr;
static float  *p_buv = nullptr;

extern "C" void kernel_launch(void* const* d_in, const int* in_sizes, int n_in,
                              void* d_out, int out_size)
{
    if (!p_wT) {  // one-time setup on the (uncaptured) correctness call
        cudaGetSymbolAddress((void**)&p_xh,  g_xh);
        cudaGetSymbolAddress((void**)&p_yh,  g_yh);
        cudaGetSymbolAddress((void**)&p_uv,  g_uv);
        cudaGetSymbolAddress((void**)&p_w,   g_w);
        cudaGetSymbolAddress((void**)&p_wT,  g_wT);
        cudaGetSymbolAddress((void**)&p_buv, g_buv);
        cudaFuncSetAttribute(persistent_gemm,
                             cudaFuncAttributeMaxDynamicSharedMemorySize, DYN_BYTES);
    }

    const float* x          = (const float*)d_in[0];
    const int*   edge_index = (const int*  )d_in[1];
    const int*   batch      = (const int*  )d_in[2];
    const float* y          = (const float*)d_in[5];
    const float* edge_label = (const float*)d_in[6];
    const float* ah_W  = (const float*)d_in[7];
    const float* ah_b  = (const float*)d_in[8];
    const float* c0_W  = (const float*)d_in[9];
    const float* c0_b  = (const float*)d_in[10];
    const float* c1_W  = (const float*)d_in[11];
    const float* c1_b  = (const float*)d_in[12];
    const float* c2_W  = (const float*)d_in[13];
    const float* c2_b  = (const float*)d_in[14];
    const float* o1_W  = (const float*)d_in[15];
    const float* o1_b  = (const float*)d_in[16];
    const float* o2_W  = (const float*)d_in[17];
    const float* o2_b  = (const float*)d_in[18];
    const float* py_W  = (const float*)d_in[19];
    const float* py_b  = (const float*)d_in[20];
    const float* pc1_W = (const float*)d_in[21];
    const float* pc1_b = (const float*)d_in[22];
    const float* pc2_W = (const float*)d_in[23];
    const float* pc2_b = (const float*)d_in[24];

    float* out = (float*)d_out;

    // ---- prep ----
    {
        Ptr8 s8;
        s8.p[0] = ah_W; s8.p[1] = c0_W; s8.p[2] = c1_W; s8.p[3] = c2_W;
        s8.p[4] = py_W;
        s8.p[5] = pc1_W;                 // W1 (rows 0..767 of pc1)
        s8.p[6] = pc1_W + 768 * DD;      // W2
        s8.p[7] = pc1_W + 1536 * DD;     // W3
        transpose8<<<dim3(DD/32, DD/32, 8), 256>>>(s8, p_wT);
        transpose_o1<<<dim3(DD/32, D3/32), 256>>>(o1_W, p_wT + 8 * (long long)SS);
        long long tot = ((long long)GG * DD + (long long)DD * DD) / 4;
        convert_yo<<<(unsigned)((tot + 255) / 256), 256>>>(y, o2_W, p_yh,
                                                           p_wT + 13 * (long long)SS);
        bias_uv<<<(2 * DD * 32 + 255) / 256, 256>>>(p_wT + 5 * (long long)SS, o2_b, p_buv);
        init_counters<<<13, 256>>>();
    }

    // ---- persistent dependency-driven GEMM pipeline ----
    BiasPack P;
    P.x = x;
    P.b[0] = nullptr; P.b[1] = nullptr;
    P.b[2] = py_b;  P.b[3] = pc1_b;
    P.b[4] = ah_b;  P.b[5] = c0_b;  P.b[6] = c1_b;  P.b[7] = c2_b;
    P.b[8] = o1_b;  P.b[9] = nullptr;
    persistent_gemm<<<296, 256, DYN_BYTES>>>(P);

    // fused edge head: relu(u+v+w) @ pc2 -> sigmoid -> out; std copy
    edge_head<<<(EE + 7) / 8, 256>>>(p_uv, p_w, edge_index, batch,
                                     pc2_W, pc2_b, edge_label, out, EE);

    (void)n_in; (void)in_sizes; (void)out_size;
}